// round 13
// baseline (speedup 1.0000x reference)
#include <cuda_runtime.h>
#include <cuda_fp16.h>

#define N_PTS 100000
#define C_IN 24
#define C_HID 144
#define C_OUT 24
#define KS 9
#define EPS 1e-5f

// ---- scratch (device globals: allocation-free rule) ----
__device__ __align__(16) __half g_x1h[(N_PTS + 1) * C_HID];
__device__ __align__(16) __half g_x2h[N_PTS * C_HID];
__device__ __align__(16) float  g_y [N_PTS * C_OUT];

__device__ float g_s1[C_HID], g_q1[C_HID];
__device__ float g_s2[C_HID], g_q2[C_HID];
__device__ float g_s3[C_OUT], g_q3[C_OUT];

__device__ __forceinline__ float relu6f(float x) { return fminf(fmaxf(x, 0.f), 6.f); }

__device__ __forceinline__ void mma16816(float* d,
                                         unsigned a0, unsigned a1, unsigned a2, unsigned a3,
                                         unsigned b0, unsigned b1) {
    asm volatile("mma.sync.aligned.m16n8k16.row.col.f32.f16.f16.f32 "
                 "{%0,%1,%2,%3}, {%4,%5,%6,%7}, {%8,%9}, {%0,%1,%2,%3};\n"
                 : "+f"(d[0]), "+f"(d[1]), "+f"(d[2]), "+f"(d[3])
                 : "r"(a0), "r"(a1), "r"(a2), "r"(a3), "r"(b0), "r"(b1));
}

__device__ __forceinline__ unsigned f2h2(float a, float b) {
    __half2 h = __floats2half2_rn(a, b);
    return *(unsigned*)&h;
}

// ---- K1: x1 = feats @ w1 via tensor cores (fp16 frag, fp32 accum + stats) ----
// 4 warps/block, each warp one m16 tile -> 64 rows/block, 18 n8 tiles.
#define T1 128
__global__ void __launch_bounds__(T1) k1_tc(const float* __restrict__ feats,
                                            const float* __restrict__ w1) {
    __shared__ __align__(4) unsigned swp[16 * C_HID];   // k-pair x n, zero padded
    __shared__ float ssum[C_HID], ssq[C_HID];

    int tid = threadIdx.x;
    int lane = tid & 31, wid = tid >> 5;
    int g = lane >> 2, c = lane & 3;

    for (int i = tid; i < 16 * C_HID; i += T1) {
        int kk = i / C_HID, n = i % C_HID;
        float lo = (2 * kk     < C_IN) ? w1[(2 * kk)     * C_HID + n] : 0.f;
        float hi = (2 * kk + 1 < C_IN) ? w1[(2 * kk + 1) * C_HID + n] : 0.f;
        swp[i] = f2h2(lo, hi);
    }
    for (int i = tid; i < C_HID; i += T1) {
        ssum[i] = 0.f; ssq[i] = 0.f;
        if (blockIdx.x == 0) { g_s2[i] = 0.f; g_q2[i] = 0.f; }
    }
    __syncthreads();

    int r  = blockIdx.x * 64 + wid * 16 + g;
    int rA = min(r, N_PTS - 1);
    int rB = min(r + 8, N_PTS - 1);
    bool vA = (r < N_PTS), vB = (r + 8 < N_PTS);

    const float2* fA = (const float2*)&feats[(size_t)rA * C_IN];
    const float2* fB = (const float2*)&feats[(size_t)rB * C_IN];

    float acc[18][4];
#pragma unroll
    for (int nt = 0; nt < 18; nt++)
#pragma unroll
        for (int j = 0; j < 4; j++) acc[nt][j] = 0.f;

    {   // k-step 0: k 0..15
        float2 f0 = fA[c], f1 = fB[c], f2 = fA[c + 4], f3 = fB[c + 4];
        unsigned a0 = f2h2(f0.x, f0.y), a1 = f2h2(f1.x, f1.y);
        unsigned a2 = f2h2(f2.x, f2.y), a3 = f2h2(f3.x, f3.y);
#pragma unroll
        for (int nt = 0; nt < 18; nt++) {
            int n = nt * 8 + g;
            mma16816(acc[nt], a0, a1, a2, a3,
                     swp[c * C_HID + n], swp[(c + 4) * C_HID + n]);
        }
    }
    {   // k-step 1: k 16..23 (+pad)
        float2 f0 = fA[8 + c], f1 = fB[8 + c];
        unsigned a0 = f2h2(f0.x, f0.y), a1 = f2h2(f1.x, f1.y);
#pragma unroll
        for (int nt = 0; nt < 18; nt++) {
            int n = nt * 8 + g;
            mma16816(acc[nt], a0, a1, 0u, 0u,
                     swp[(8 + c) * C_HID + n], swp[(12 + c) * C_HID + n]);
        }
    }

#pragma unroll
    for (int nt = 0; nt < 18; nt++) {
        int n = nt * 8 + 2 * c;
        float c0 = acc[nt][0], c1 = acc[nt][1], c2 = acc[nt][2], c3 = acc[nt][3];
        if (vA) *(unsigned*)&g_x1h[(size_t)r * C_HID + n] = f2h2(c0, c1);
        if (vB) *(unsigned*)&g_x1h[(size_t)(r + 8) * C_HID + n] = f2h2(c2, c3);
        float s0 = (vA ? c0 : 0.f) + (vB ? c2 : 0.f);
        float s1 = (vA ? c1 : 0.f) + (vB ? c3 : 0.f);
        float q0 = (vA ? c0 * c0 : 0.f) + (vB ? c2 * c2 : 0.f);
        float q1 = (vA ? c1 * c1 : 0.f) + (vB ? c3 * c3 : 0.f);
#pragma unroll
        for (int off = 16; off >= 4; off >>= 1) {
            s0 += __shfl_down_sync(0xffffffffu, s0, off);
            s1 += __shfl_down_sync(0xffffffffu, s1, off);
            q0 += __shfl_down_sync(0xffffffffu, q0, off);
            q1 += __shfl_down_sync(0xffffffffu, q1, off);
        }
        if (g == 0) {
            atomicAdd(&ssum[n],     s0);
            atomicAdd(&ssum[n + 1], s1);
            atomicAdd(&ssq[n],      q0);
            atomicAdd(&ssq[n + 1],  q1);
        }
    }
    __syncthreads();
    for (int i = tid; i < C_HID; i += T1) {
        atomicAdd(&g_s1[i], ssum[i]);
        atomicAdd(&g_q1[i], ssq[i]);
    }
}

// ---- K2: x1 <- relu6(bn1(x1)), fp16, 8 halfs/thread, vector LDS ----
#define TA 256
__global__ void __launch_bounds__(TA) k2_act(const float* __restrict__ gg,
                                             const float* __restrict__ bb) {
    __shared__ __align__(16) float ssc[C_HID], ssh[C_HID];
    int tid = threadIdx.x;
    if (tid < C_HID) {
        float m = g_s1[tid] * (1.0f / N_PTS);
        float v = g_q1[tid] * (1.0f / N_PTS) - m * m;
        float sc = gg[tid] * rsqrtf(v + EPS);
        ssc[tid] = sc;
        ssh[tid] = bb[tid] - m * sc;
    }
    __syncthreads();

    size_t i = (size_t)blockIdx.x * TA + tid;        // uint4 = 8 halfs
    const size_t total = (size_t)N_PTS * C_HID / 8;  // 144/8=18 per row, aligned
    if (i < total) {
        int cb = (int)(i % 18) * 8;
        uint4 u = *(const uint4*)&g_x1h[i * 8];
        float4 scA = *(const float4*)&ssc[cb];
        float4 scB = *(const float4*)&ssc[cb + 4];
        float4 shA = *(const float4*)&ssh[cb];
        float4 shB = *(const float4*)&ssh[cb + 4];
        float scr[8] = {scA.x, scA.y, scA.z, scA.w, scB.x, scB.y, scB.z, scB.w};
        float shr[8] = {shA.x, shA.y, shA.z, shA.w, shB.x, shB.y, shB.z, shB.w};
        unsigned int* up = &u.x;
        uint4 o;
        unsigned int* op = &o.x;
#pragma unroll
        for (int j = 0; j < 4; j++) {
            float2 f = __half22float2(*(__half2*)&up[j]);
            float v0 = relu6f(fmaf(f.x, scr[2 * j],     shr[2 * j]));
            float v1 = relu6f(fmaf(f.y, scr[2 * j + 1], shr[2 * j + 1]));
            op[j] = f2h2(v0, v1);
        }
        *(uint4*)&g_x1h[i * 8] = o;
    }
}

// ---- K3: pure weighted gather conv + BN2 stats (x2 stored RAW fp16) ----
#define R3 64
#define T3 288
__global__ void __launch_bounds__(T3) k3_conv(const float* __restrict__ w2,
                                              const int* __restrict__ in_idx) {
    __shared__ int snbr[R3][KS];
    __shared__ __align__(8) float rs[4][C_HID], rq[4][C_HID];

    int tid = threadIdx.x;
    int row0 = blockIdx.x * R3;

    if (blockIdx.x == 0 && tid < C_OUT) { g_s3[tid] = 0.f; g_q3[tid] = 0.f; }

#pragma unroll
    for (int t = 0; t < 2; t++) {
        int i = tid + t * T3;
        int k = i / R3, r = i % R3;
        int rr = row0 + r;
        snbr[r][k] = (rr < N_PTS) ? in_idx[k * N_PTS + rr] : N_PTS;
    }
    __syncthreads();

    int cg = tid % 72, rl = tid / 72;
    int cb = cg * 2;

    float2 wk[KS];
#pragma unroll
    for (int k = 0; k < KS; k++) wk[k] = *(const float2*)&w2[k * C_HID + cb];

    float s0 = 0.f, s1 = 0.f, q0 = 0.f, q1 = 0.f;
#pragma unroll 2
    for (int j = 0; j < 16; j++) {
        int r = rl * 16 + j;
        unsigned int h[KS];
#pragma unroll
        for (int k = 0; k < KS; k++)
            h[k] = *(const unsigned int*)&g_x1h[snbr[r][k] * C_HID + cb];

        float a0 = 0.f, a1 = 0.f;
#pragma unroll
        for (int k = 0; k < KS; k++) {
            float2 x = __half22float2(*(__half2*)&h[k]);
            a0 = fmaf(wk[k].x, x.x, a0);
            a1 = fmaf(wk[k].y, x.y, a1);
        }
        int rr = row0 + r;
        if (rr < N_PTS) {
            *(unsigned int*)&g_x2h[(size_t)rr * C_HID + cb] = f2h2(a0, a1);
            s0 += a0; q0 += a0 * a0;
            s1 += a1; q1 += a1 * a1;
        }
    }
    rs[rl][cb] = s0; rs[rl][cb + 1] = s1;
    rq[rl][cb] = q0; rq[rl][cb + 1] = q1;
    __syncthreads();
    if (tid < C_HID) {
        float s = rs[0][tid] + rs[1][tid] + rs[2][tid] + rs[3][tid];
        float q = rq[0][tid] + rq[1][tid] + rq[2][tid] + rq[3][tid];
        atomicAdd(&g_s2[tid], s);
        atomicAdd(&g_q2[tid], q);
    }
}

// ---- K5: y = relu6(bn2(x2)) @ w3 via mma.m16n8k16, activation fused ----
// R5T=128: grid 782, 2 m-tiles/warp -> higher occupancy than R12's 391-block grid.
#define T5 128
#define R5T 128
__global__ void __launch_bounds__(T5) k5_tc(const float* __restrict__ w3,
                                            const float* __restrict__ g2,
                                            const float* __restrict__ b2) {
    __shared__ __align__(4) unsigned int swp[72 * C_OUT];   // half2 (k,k+1) pairs
    __shared__ __align__(8) float ssc[C_HID], ssh[C_HID];
    __shared__ float ssum[C_OUT], ssq[C_OUT];

    int tid = threadIdx.x;
    int lane = tid & 31, wid = tid >> 5;
    int g = lane >> 2, c = lane & 3;

    for (int i = tid; i < 72 * C_OUT; i += T5) {
        int kk = i / C_OUT, n = i % C_OUT;
        swp[i] = f2h2(w3[(2 * kk) * C_OUT + n], w3[(2 * kk + 1) * C_OUT + n]);
    }
    for (int i = tid; i < C_HID; i += T5) {
        float m = g_s2[i] * (1.0f / N_PTS);
        float v = g_q2[i] * (1.0f / N_PTS) - m * m;
        float sc = g2[i] * rsqrtf(v + EPS);
        ssc[i] = sc;
        ssh[i] = b2[i] - m * sc;
    }
    if (tid < C_OUT) { ssum[tid] = 0.f; ssq[tid] = 0.f; }
    __syncthreads();

    int row0 = blockIdx.x * R5T + wid * 32;

    float acc[2][3][4];
#pragma unroll
    for (int mt = 0; mt < 2; mt++)
#pragma unroll
        for (int nt = 0; nt < 3; nt++)
#pragma unroll
            for (int j = 0; j < 4; j++) acc[mt][nt][j] = 0.f;

#pragma unroll
    for (int ks = 0; ks < 9; ks++) {
        int k0 = ks * 16;
        unsigned int b[3][2];
        int kb = (k0 >> 1) + c;
#pragma unroll
        for (int nt = 0; nt < 3; nt++) {
            int n = nt * 8 + g;
            b[nt][0] = swp[kb * C_OUT + n];
            b[nt][1] = swp[(kb + 4) * C_OUT + n];
        }
        int chL = k0 + 2 * c;
        int chH = chL + 8;
        float2 scL = *(const float2*)&ssc[chL];
        float2 shL = *(const float2*)&ssh[chL];
        float2 scH = *(const float2*)&ssc[chH];
        float2 shH = *(const float2*)&ssh[chH];
#pragma unroll
        for (int mt = 0; mt < 2; mt++) {
            int r  = row0 + mt * 16 + g;
            int rA = min(r, N_PTS - 1);
            int rB = min(r + 8, N_PTS - 1);
            unsigned int a0 = *(const unsigned int*)&g_x2h[(size_t)rA * C_HID + chL];
            unsigned int a1 = *(const unsigned int*)&g_x2h[(size_t)rB * C_HID + chL];
            unsigned int a2 = *(const unsigned int*)&g_x2h[(size_t)rA * C_HID + chH];
            unsigned int a3 = *(const unsigned int*)&g_x2h[(size_t)rB * C_HID + chH];
            float2 f;
            f = __half22float2(*(__half2*)&a0);
            a0 = f2h2(relu6f(fmaf(f.x, scL.x, shL.x)), relu6f(fmaf(f.y, scL.y, shL.y)));
            f = __half22float2(*(__half2*)&a1);
            a1 = f2h2(relu6f(fmaf(f.x, scL.x, shL.x)), relu6f(fmaf(f.y, scL.y, shL.y)));
            f = __half22float2(*(__half2*)&a2);
            a2 = f2h2(relu6f(fmaf(f.x, scH.x, shH.x)), relu6f(fmaf(f.y, scH.y, shH.y)));
            f = __half22float2(*(__half2*)&a3);
            a3 = f2h2(relu6f(fmaf(f.x, scH.x, shH.x)), relu6f(fmaf(f.y, scH.y, shH.y)));
#pragma unroll
            for (int nt = 0; nt < 3; nt++)
                mma16816(acc[mt][nt], a0, a1, a2, a3, b[nt][0], b[nt][1]);
        }
    }

    float s[3][2], q[3][2];
#pragma unroll
    for (int nt = 0; nt < 3; nt++) { s[nt][0] = s[nt][1] = 0.f; q[nt][0] = q[nt][1] = 0.f; }

#pragma unroll
    for (int mt = 0; mt < 2; mt++) {
        int r = row0 + mt * 16 + g;
#pragma unroll
        for (int nt = 0; nt < 3; nt++) {
            int n = nt * 8 + 2 * c;
            if (r < N_PTS) {
                float c0 = acc[mt][nt][0], c1 = acc[mt][nt][1];
                *(float2*)&g_y[(size_t)r * C_OUT + n] = make_float2(c0, c1);
                s[nt][0] += c0; q[nt][0] += c0 * c0;
                s[nt][1] += c1; q[nt][1] += c1 * c1;
            }
            if (r + 8 < N_PTS) {
                float c2 = acc[mt][nt][2], c3 = acc[mt][nt][3];
                *(float2*)&g_y[(size_t)(r + 8) * C_OUT + n] = make_float2(c2, c3);
                s[nt][0] += c2; q[nt][0] += c2 * c2;
                s[nt][1] += c3; q[nt][1] += c3 * c3;
            }
        }
    }
#pragma unroll
    for (int off = 16; off >= 4; off >>= 1) {
#pragma unroll
        for (int nt = 0; nt < 3; nt++) {
#pragma unroll
            for (int j = 0; j < 2; j++) {
                s[nt][j] += __shfl_down_sync(0xffffffffu, s[nt][j], off);
                q[nt][j] += __shfl_down_sync(0xffffffffu, q[nt][j], off);
            }
        }
    }
    if (g == 0) {
#pragma unroll
        for (int nt = 0; nt < 3; nt++) {
            int n = nt * 8 + 2 * c;
            atomicAdd(&ssum[n],     s[nt][0]);
            atomicAdd(&ssum[n + 1], s[nt][1]);
            atomicAdd(&ssq[n],      q[nt][0]);
            atomicAdd(&ssq[n + 1],  q[nt][1]);
        }
    }
    __syncthreads();
    if (tid < C_OUT) {
        atomicAdd(&g_s3[tid], ssum[tid]);
        atomicAdd(&g_q3[tid], ssq[tid]);
    }
}

// ---- K7: out = bn3(y) + feats (float4); block0 zeroes stage-1 accumulators ----
__global__ void k7_out(const float* __restrict__ feats, float* __restrict__ out,
                       const float* __restrict__ g3, const float* __restrict__ b3) {
    __shared__ float ssc[C_OUT], ssh[C_OUT];
    int tid = threadIdx.x;
    if (blockIdx.x == 0 && tid < C_HID) { g_s1[tid] = 0.f; g_q1[tid] = 0.f; }
    if (tid < C_OUT) {
        float m = g_s3[tid] * (1.0f / N_PTS);
        float v = g_q3[tid] * (1.0f / N_PTS) - m * m;
        float sc = g3[tid] * rsqrtf(v + EPS);
        ssc[tid] = sc;
        ssh[tid] = b3[tid] - m * sc;
    }
    __syncthreads();

    int i = blockIdx.x * blockDim.x + tid;   // float4 index
    if (i < N_PTS * C_OUT / 4) {
        int cb = (i % 6) * 4;
        float4 y  = *(const float4*)&g_y[i * 4];
        float4 f  = *(const float4*)&feats[i * 4];
        float4 o;
        o.x = fmaf(y.x, ssc[cb + 0], ssh[cb + 0]) + f.x;
        o.y = fmaf(y.y, ssc[cb + 1], ssh[cb + 1]) + f.y;
        o.z = fmaf(y.z, ssc[cb + 2], ssh[cb + 2]) + f.z;
        o.w = fmaf(y.w, ssc[cb + 3], ssh[cb + 3]) + f.w;
        *(float4*)&out[i * 4] = o;
    }
}

extern "C" void kernel_launch(void* const* d_in, const int* in_sizes, int n_in,
                              void* d_out, int out_size) {
    const float* feats = (const float*)d_in[0];
    const float* w1    = (const float*)d_in[1];
    const float* g1    = (const float*)d_in[2];
    const float* b1    = (const float*)d_in[3];
    const float* w2    = (const float*)d_in[4];
    const float* g2    = (const float*)d_in[5];
    const float* b2    = (const float*)d_in[6];
    const float* w3    = (const float*)d_in[7];
    const float* g3    = (const float*)d_in[8];
    const float* b3    = (const float*)d_in[9];
    const int*   in_idx = (const int*)d_in[10];
    float* out = (float*)d_out;

    int nb1 = (N_PTS + 63) / 64;
    k1_tc<<<nb1, T1>>>(feats, w1);

    unsigned nba = (unsigned)(((size_t)N_PTS * C_HID / 8 + TA - 1) / TA);
    k2_act<<<nba, TA>>>(g1, b1);

    int nb3 = (N_PTS + R3 - 1) / R3;
    k3_conv<<<nb3, T3>>>(w2, in_idx);

    int nb5 = (N_PTS + R5T - 1) / R5T;
    k5_tc<<<nb5, T5>>>(w3, g2, b2);

    int total4 = N_PTS * C_OUT / 4;
    k7_out<<<(total4 + 255) / 256, 256>>>(feats, out, g3, b3);
}

// round 14
// speedup vs baseline: 1.0554x; 1.0554x over previous
#include <cuda_runtime.h>
#include <cuda_fp16.h>

#define N_PTS 100000
#define C_IN 24
#define C_HID 144
#define C_OUT 24
#define KS 9
#define EPS 1e-5f

// ---- scratch (device globals: allocation-free rule) ----
__device__ __align__(16) __half g_x1h[(N_PTS + 1) * C_HID];
__device__ __align__(16) __half g_x2h[N_PTS * C_HID];
__device__ __align__(16) float  g_y [N_PTS * C_OUT];

__device__ float g_s1[C_HID], g_q1[C_HID];
__device__ float g_s2[C_HID], g_q2[C_HID];
__device__ float g_s3[C_OUT], g_q3[C_OUT];

__device__ __forceinline__ float relu6f(float x) { return fminf(fmaxf(x, 0.f), 6.f); }

__device__ __forceinline__ void mma16816(float* d,
                                         unsigned a0, unsigned a1, unsigned a2, unsigned a3,
                                         unsigned b0, unsigned b1) {
    asm volatile("mma.sync.aligned.m16n8k16.row.col.f32.f16.f16.f32 "
                 "{%0,%1,%2,%3}, {%4,%5,%6,%7}, {%8,%9}, {%0,%1,%2,%3};\n"
                 : "+f"(d[0]), "+f"(d[1]), "+f"(d[2]), "+f"(d[3])
                 : "r"(a0), "r"(a1), "r"(a2), "r"(a3), "r"(b0), "r"(b1));
}

__device__ __forceinline__ unsigned f2h2(float a, float b) {
    __half2 h = __floats2half2_rn(a, b);
    return *(unsigned*)&h;
}

// ---- K1: x1 = feats @ w1 (scalar fp32, fp16 out); block0 zeroes stage-2 accums ----
#define R1 64
#define T1 288
__global__ void __launch_bounds__(T1) k1_gemm1(const float* __restrict__ feats,
                                               const float* __restrict__ w1) {
    __shared__ __align__(16) float sfT[C_IN][R1];
    __shared__ __align__(16) float sw1[C_IN * C_HID];
    __shared__ __align__(16) float rs[8][C_HID], rq[8][C_HID];

    int tid = threadIdx.x;
    int row0 = blockIdx.x * R1;

    if (blockIdx.x == 0 && tid < C_HID) { g_s2[tid] = 0.f; g_q2[tid] = 0.f; }

    for (int i = tid; i < C_IN * C_HID; i += T1) sw1[i] = w1[i];
    for (int i = tid; i < R1 * C_IN; i += T1) {
        int r = i / C_IN, k = i % C_IN;
        int rr = row0 + r;
        sfT[k][r] = (rr < N_PTS) ? feats[rr * C_IN + k] : 0.f;
    }
    __syncthreads();

    int c4 = tid % 36, rg = tid / 36;
    int cb = c4 * 4;
    float4 acc[8];
#pragma unroll
    for (int j = 0; j < 8; j++) acc[j] = make_float4(0.f, 0.f, 0.f, 0.f);

#pragma unroll
    for (int k = 0; k < C_IN; k++) {
        float4 w  = *(const float4*)&sw1[k * C_HID + cb];
        float4 xa = *(const float4*)&sfT[k][rg * 8];
        float4 xb = *(const float4*)&sfT[k][rg * 8 + 4];
        float xr[8] = {xa.x, xa.y, xa.z, xa.w, xb.x, xb.y, xb.z, xb.w};
#pragma unroll
        for (int j = 0; j < 8; j++) {
            acc[j].x = fmaf(w.x, xr[j], acc[j].x);
            acc[j].y = fmaf(w.y, xr[j], acc[j].y);
            acc[j].z = fmaf(w.z, xr[j], acc[j].z);
            acc[j].w = fmaf(w.w, xr[j], acc[j].w);
        }
    }

    float4 s4 = make_float4(0.f, 0.f, 0.f, 0.f), q4 = s4;
#pragma unroll
    for (int j = 0; j < 8; j++) {
        int rr = row0 + rg * 8 + j;
        if (rr < N_PTS) {
            uint2 pk;
            pk.x = f2h2(acc[j].x, acc[j].y);
            pk.y = f2h2(acc[j].z, acc[j].w);
            *(uint2*)&g_x1h[(size_t)rr * C_HID + cb] = pk;
        }
        s4.x += acc[j].x; s4.y += acc[j].y; s4.z += acc[j].z; s4.w += acc[j].w;
        q4.x += acc[j].x * acc[j].x; q4.y += acc[j].y * acc[j].y;
        q4.z += acc[j].z * acc[j].z; q4.w += acc[j].w * acc[j].w;
    }
    *(float4*)&rs[rg][cb] = s4;
    *(float4*)&rq[rg][cb] = q4;
    __syncthreads();
    if (tid < C_HID) {
        float s = 0.f, q = 0.f;
#pragma unroll
        for (int g = 0; g < 8; g++) { s += rs[g][tid]; q += rq[g][tid]; }
        atomicAdd(&g_s1[tid], s);
        atomicAdd(&g_q1[tid], q);
    }
}

// ---- K2: x1 <- relu6(bn1(x1)), fp16, 8 halfs/thread, vector LDS ----
#define TA 256
__global__ void __launch_bounds__(TA) k2_act(const float* __restrict__ gg,
                                             const float* __restrict__ bb) {
    __shared__ __align__(16) float ssc[C_HID], ssh[C_HID];
    int tid = threadIdx.x;
    if (tid < C_HID) {
        float m = g_s1[tid] * (1.0f / N_PTS);
        float v = g_q1[tid] * (1.0f / N_PTS) - m * m;
        float sc = gg[tid] * rsqrtf(v + EPS);
        ssc[tid] = sc;
        ssh[tid] = bb[tid] - m * sc;
    }
    __syncthreads();

    size_t i = (size_t)blockIdx.x * TA + tid;        // uint4 = 8 halfs
    const size_t total = (size_t)N_PTS * C_HID / 8;  // 144/8=18 per row, aligned
    if (i < total) {
        int cb = (int)(i % 18) * 8;
        uint4 u = *(const uint4*)&g_x1h[i * 8];
        float4 scA = *(const float4*)&ssc[cb];
        float4 scB = *(const float4*)&ssc[cb + 4];
        float4 shA = *(const float4*)&ssh[cb];
        float4 shB = *(const float4*)&ssh[cb + 4];
        float scr[8] = {scA.x, scA.y, scA.z, scA.w, scB.x, scB.y, scB.z, scB.w};
        float shr[8] = {shA.x, shA.y, shA.z, shA.w, shB.x, shB.y, shB.z, shB.w};
        unsigned int* up = &u.x;
        uint4 o;
        unsigned int* op = &o.x;
#pragma unroll
        for (int j = 0; j < 4; j++) {
            float2 f = __half22float2(*(__half2*)&up[j]);
            float v0 = relu6f(fmaf(f.x, scr[2 * j],     shr[2 * j]));
            float v1 = relu6f(fmaf(f.y, scr[2 * j + 1], shr[2 * j + 1]));
            op[j] = f2h2(v0, v1);
        }
        *(uint4*)&g_x1h[i * 8] = o;
    }
}

// ---- K3: pure weighted gather conv + BN2 stats; 4 channels/thread (uint2 gathers) ----
#define R3 64
#define T3 288   // 36 channel-quads x 8 row-lanes; each thread does 8 rows
__global__ void __launch_bounds__(T3) k3_conv(const float* __restrict__ w2,
                                              const int* __restrict__ in_idx) {
    __shared__ int snbr[R3][KS];
    __shared__ __align__(16) float sw2[KS * C_HID];
    __shared__ __align__(16) float rs[8][C_HID], rq[8][C_HID];

    int tid = threadIdx.x;
    int row0 = blockIdx.x * R3;

    if (blockIdx.x == 0 && tid < C_OUT) { g_s3[tid] = 0.f; g_q3[tid] = 0.f; }

    for (int i = tid; i < KS * C_HID; i += T3) sw2[i] = w2[i];
#pragma unroll
    for (int t = 0; t < 2; t++) {
        int i = tid + t * T3;
        int k = i / R3, r = i % R3;
        int rr = row0 + r;
        snbr[r][k] = (rr < N_PTS) ? in_idx[k * N_PTS + rr] : N_PTS;
    }
    __syncthreads();

    int cg = tid % 36, rl = tid / 36;    // 4 channels, rows rl*8..rl*8+7
    int cb = cg * 4;

    float4 s4 = make_float4(0.f, 0.f, 0.f, 0.f), q4 = s4;
#pragma unroll 2
    for (int j = 0; j < 8; j++) {
        int r = rl * 8 + j;
        uint2 h[KS];
#pragma unroll
        for (int k = 0; k < KS; k++)   // sentinel row N_PTS is all zeros -> safe
            h[k] = *(const uint2*)&g_x1h[(size_t)snbr[r][k] * C_HID + cb];

        float4 a = make_float4(0.f, 0.f, 0.f, 0.f);
#pragma unroll
        for (int k = 0; k < KS; k++) {
            float4 w = *(const float4*)&sw2[k * C_HID + cb];
            float2 lo = __half22float2(*(__half2*)&h[k].x);
            float2 hi = __half22float2(*(__half2*)&h[k].y);
            a.x = fmaf(w.x, lo.x, a.x);
            a.y = fmaf(w.y, lo.y, a.y);
            a.z = fmaf(w.z, hi.x, a.z);
            a.w = fmaf(w.w, hi.y, a.w);
        }
        int rr = row0 + r;
        if (rr < N_PTS) {
            uint2 pk;
            pk.x = f2h2(a.x, a.y);
            pk.y = f2h2(a.z, a.w);
            *(uint2*)&g_x2h[(size_t)rr * C_HID + cb] = pk;
            s4.x += a.x; s4.y += a.y; s4.z += a.z; s4.w += a.w;
            q4.x += a.x * a.x; q4.y += a.y * a.y;
            q4.z += a.z * a.z; q4.w += a.w * a.w;
        }
    }
    *(float4*)&rs[rl][cb] = s4;
    *(float4*)&rq[rl][cb] = q4;
    __syncthreads();
    if (tid < C_HID) {
        float s = 0.f, q = 0.f;
#pragma unroll
        for (int g = 0; g < 8; g++) { s += rs[g][tid]; q += rq[g][tid]; }
        atomicAdd(&g_s2[tid], s);
        atomicAdd(&g_q2[tid], q);
    }
}

// ---- K5: y = relu6(bn2(x2)) @ w3 via mma.m16n8k16, activation fused (R12 config) ----
#define T5 128
#define R5T 256
__global__ void __launch_bounds__(T5) k5_tc(const float* __restrict__ w3,
                                            const float* __restrict__ g2,
                                            const float* __restrict__ b2) {
    __shared__ __align__(4) unsigned int swp[72 * C_OUT];   // half2 (k,k+1) pairs
    __shared__ __align__(8) float ssc[C_HID], ssh[C_HID];
    __shared__ float ssum[C_OUT], ssq[C_OUT];

    int tid = threadIdx.x;
    int lane = tid & 31, wid = tid >> 5;
    int g = lane >> 2, c = lane & 3;

    for (int i = tid; i < 72 * C_OUT; i += T5) {
        int kk = i / C_OUT, n = i % C_OUT;
        swp[i] = f2h2(w3[(2 * kk) * C_OUT + n], w3[(2 * kk + 1) * C_OUT + n]);
    }
    for (int i = tid; i < C_HID; i += T5) {
        float m = g_s2[i] * (1.0f / N_PTS);
        float v = g_q2[i] * (1.0f / N_PTS) - m * m;
        float sc = g2[i] * rsqrtf(v + EPS);
        ssc[i] = sc;
        ssh[i] = b2[i] - m * sc;
    }
    if (tid < C_OUT) { ssum[tid] = 0.f; ssq[tid] = 0.f; }
    __syncthreads();

    int row0 = blockIdx.x * R5T + wid * 64;

    float acc[4][3][4];
#pragma unroll
    for (int mt = 0; mt < 4; mt++)
#pragma unroll
        for (int nt = 0; nt < 3; nt++)
#pragma unroll
            for (int j = 0; j < 4; j++) acc[mt][nt][j] = 0.f;

#pragma unroll
    for (int ks = 0; ks < 9; ks++) {
        int k0 = ks * 16;
        unsigned int b[3][2];
        int kb = (k0 >> 1) + c;
#pragma unroll
        for (int nt = 0; nt < 3; nt++) {
            int n = nt * 8 + g;
            b[nt][0] = swp[kb * C_OUT + n];
            b[nt][1] = swp[(kb + 4) * C_OUT + n];
        }
        int chL = k0 + 2 * c;
        int chH = chL + 8;
        float2 scL = *(const float2*)&ssc[chL];
        float2 shL = *(const float2*)&ssh[chL];
        float2 scH = *(const float2*)&ssc[chH];
        float2 shH = *(const float2*)&ssh[chH];
#pragma unroll
        for (int mt = 0; mt < 4; mt++) {
            int r  = row0 + mt * 16 + g;
            int rA = min(r, N_PTS - 1);
            int rB = min(r + 8, N_PTS - 1);
            unsigned int a0 = *(const unsigned int*)&g_x2h[(size_t)rA * C_HID + chL];
            unsigned int a1 = *(const unsigned int*)&g_x2h[(size_t)rB * C_HID + chL];
            unsigned int a2 = *(const unsigned int*)&g_x2h[(size_t)rA * C_HID + chH];
            unsigned int a3 = *(const unsigned int*)&g_x2h[(size_t)rB * C_HID + chH];
            float2 f;
            f = __half22float2(*(__half2*)&a0);
            a0 = f2h2(relu6f(fmaf(f.x, scL.x, shL.x)), relu6f(fmaf(f.y, scL.y, shL.y)));
            f = __half22float2(*(__half2*)&a1);
            a1 = f2h2(relu6f(fmaf(f.x, scL.x, shL.x)), relu6f(fmaf(f.y, scL.y, shL.y)));
            f = __half22float2(*(__half2*)&a2);
            a2 = f2h2(relu6f(fmaf(f.x, scH.x, shH.x)), relu6f(fmaf(f.y, scH.y, shH.y)));
            f = __half22float2(*(__half2*)&a3);
            a3 = f2h2(relu6f(fmaf(f.x, scH.x, shH.x)), relu6f(fmaf(f.y, scH.y, shH.y)));
#pragma unroll
            for (int nt = 0; nt < 3; nt++)
                mma16816(acc[mt][nt], a0, a1, a2, a3, b[nt][0], b[nt][1]);
        }
    }

    float s[3][2], q[3][2];
#pragma unroll
    for (int nt = 0; nt < 3; nt++) { s[nt][0] = s[nt][1] = 0.f; q[nt][0] = q[nt][1] = 0.f; }

#pragma unroll
    for (int mt = 0; mt < 4; mt++) {
        int r = row0 + mt * 16 + g;
#pragma unroll
        for (int nt = 0; nt < 3; nt++) {
            int n = nt * 8 + 2 * c;
            if (r < N_PTS) {
                float c0 = acc[mt][nt][0], c1 = acc[mt][nt][1];
                *(float2*)&g_y[(size_t)r * C_OUT + n] = make_float2(c0, c1);
                s[nt][0] += c0; q[nt][0] += c0 * c0;
                s[nt][1] += c1; q[nt][1] += c1 * c1;
            }
            if (r + 8 < N_PTS) {
                float c2 = acc[mt][nt][2], c3 = acc[mt][nt][3];
                *(float2*)&g_y[(size_t)(r + 8) * C_OUT + n] = make_float2(c2, c3);
                s[nt][0] += c2; q[nt][0] += c2 * c2;
                s[nt][1] += c3; q[nt][1] += c3 * c3;
            }
        }
    }
#pragma unroll
    for (int off = 16; off >= 4; off >>= 1) {
#pragma unroll
        for (int nt = 0; nt < 3; nt++) {
#pragma unroll
            for (int j = 0; j < 2; j++) {
                s[nt][j] += __shfl_down_sync(0xffffffffu, s[nt][j], off);
                q[nt][j] += __shfl_down_sync(0xffffffffu, q[nt][j], off);
            }
        }
    }
    if (g == 0) {
#pragma unroll
        for (int nt = 0; nt < 3; nt++) {
            int n = nt * 8 + 2 * c;
            atomicAdd(&ssum[n],     s[nt][0]);
            atomicAdd(&ssum[n + 1], s[nt][1]);
            atomicAdd(&ssq[n],      q[nt][0]);
            atomicAdd(&ssq[n + 1],  q[nt][1]);
        }
    }
    __syncthreads();
    if (tid < C_OUT) {
        atomicAdd(&g_s3[tid], ssum[tid]);
        atomicAdd(&g_q3[tid], ssq[tid]);
    }
}

// ---- K7: out = bn3(y) + feats (float4); block0 zeroes stage-1 accumulators ----
__global__ void k7_out(const float* __restrict__ feats, float* __restrict__ out,
                       const float* __restrict__ g3, const float* __restrict__ b3) {
    __shared__ float ssc[C_OUT], ssh[C_OUT];
    int tid = threadIdx.x;
    if (blockIdx.x == 0 && tid < C_HID) { g_s1[tid] = 0.f; g_q1[tid] = 0.f; }
    if (tid < C_OUT) {
        float m = g_s3[tid] * (1.0f / N_PTS);
        float v = g_q3[tid] * (1.0f / N_PTS) - m * m;
        float sc = g3[tid] * rsqrtf(v + EPS);
        ssc[tid] = sc;
        ssh[tid] = b3[tid] - m * sc;
    }
    __syncthreads();

    int i = blockIdx.x * blockDim.x + tid;   // float4 index
    if (i < N_PTS * C_OUT / 4) {
        int cb = (i % 6) * 4;
        float4 y  = *(const float4*)&g_y[i * 4];
        float4 f  = *(const float4*)&feats[i * 4];
        float4 o;
        o.x = fmaf(y.x, ssc[cb + 0], ssh[cb + 0]) + f.x;
        o.y = fmaf(y.y, ssc[cb + 1], ssh[cb + 1]) + f.y;
        o.z = fmaf(y.z, ssc[cb + 2], ssh[cb + 2]) + f.z;
        o.w = fmaf(y.w, ssc[cb + 3], ssh[cb + 3]) + f.w;
        *(float4*)&out[i * 4] = o;
    }
}

extern "C" void kernel_launch(void* const* d_in, const int* in_sizes, int n_in,
                              void* d_out, int out_size) {
    const float* feats = (const float*)d_in[0];
    const float* w1    = (const float*)d_in[1];
    const float* g1    = (const float*)d_in[2];
    const float* b1    = (const float*)d_in[3];
    const float* w2    = (const float*)d_in[4];
    const float* g2    = (const float*)d_in[5];
    const float* b2    = (const float*)d_in[6];
    const float* w3    = (const float*)d_in[7];
    const float* g3    = (const float*)d_in[8];
    const float* b3    = (const float*)d_in[9];
    const int*   in_idx = (const int*)d_in[10];
    float* out = (float*)d_out;

    int nb1 = (N_PTS + R1 - 1) / R1;
    k1_gemm1<<<nb1, T1>>>(feats, w1);

    unsigned nba = (unsigned)(((size_t)N_PTS * C_HID / 8 + TA - 1) / TA);
    k2_act<<<nba, TA>>>(g1, b1);

    int nb3 = (N_PTS + R3 - 1) / R3;
    k3_conv<<<nb3, T3>>>(w2, in_idx);

    int nb5 = (N_PTS + R5T - 1) / R5T;
    k5_tc<<<nb5, T5>>>(w3, g2, b2);

    int total4 = N_PTS * C_OUT / 4;
    k7_out<<<(total4 + 255) / 256, 256>>>(feats, out, g3, b3);
}

// round 15
// speedup vs baseline: 1.1220x; 1.0632x over previous
#include <cuda_runtime.h>
#include <cuda_fp16.h>

#define N_PTS 100000
#define C_IN 24
#define C_HID 144
#define C_OUT 24
#define KS 9
#define EPS 1e-5f

// ---- scratch (device globals: allocation-free rule) ----
__device__ __align__(16) __half g_x1h[(N_PTS + 1) * C_HID];
__device__ __align__(16) __half g_x2h[N_PTS * C_HID];
__device__ __align__(16) float  g_y [N_PTS * C_OUT];

__device__ float g_s1[C_HID], g_q1[C_HID];
__device__ float g_s2[C_HID], g_q2[C_HID];
__device__ float g_s3[C_OUT], g_q3[C_OUT];

__device__ __forceinline__ float relu6f(float x) { return fminf(fmaxf(x, 0.f), 6.f); }

__device__ __forceinline__ void mma16816(float* d,
                                         unsigned a0, unsigned a1, unsigned a2, unsigned a3,
                                         unsigned b0, unsigned b1) {
    asm volatile("mma.sync.aligned.m16n8k16.row.col.f32.f16.f16.f32 "
                 "{%0,%1,%2,%3}, {%4,%5,%6,%7}, {%8,%9}, {%0,%1,%2,%3};\n"
                 : "+f"(d[0]), "+f"(d[1]), "+f"(d[2]), "+f"(d[3])
                 : "r"(a0), "r"(a1), "r"(a2), "r"(a3), "r"(b0), "r"(b1));
}

__device__ __forceinline__ unsigned f2h2(float a, float b) {
    __half2 h = __floats2half2_rn(a, b);
    return *(unsigned*)&h;
}

// ---- K1: x1 = feats @ w1 (scalar fp32, fp16 out); block0 zeroes stage-2 accums ----
#define R1 64
#define T1 288
__global__ void __launch_bounds__(T1) k1_gemm1(const float* __restrict__ feats,
                                               const float* __restrict__ w1) {
    __shared__ __align__(16) float sfT[C_IN][R1];
    __shared__ __align__(16) float sw1[C_IN * C_HID];
    __shared__ __align__(16) float rs[8][C_HID], rq[8][C_HID];

    int tid = threadIdx.x;
    int row0 = blockIdx.x * R1;

    if (blockIdx.x == 0 && tid < C_HID) { g_s2[tid] = 0.f; g_q2[tid] = 0.f; }

    for (int i = tid; i < C_IN * C_HID; i += T1) sw1[i] = w1[i];
    for (int i = tid; i < R1 * C_IN; i += T1) {
        int r = i / C_IN, k = i % C_IN;
        int rr = row0 + r;
        sfT[k][r] = (rr < N_PTS) ? feats[rr * C_IN + k] : 0.f;
    }
    __syncthreads();

    int c4 = tid % 36, rg = tid / 36;
    int cb = c4 * 4;
    float4 acc[8];
#pragma unroll
    for (int j = 0; j < 8; j++) acc[j] = make_float4(0.f, 0.f, 0.f, 0.f);

#pragma unroll
    for (int k = 0; k < C_IN; k++) {
        float4 w  = *(const float4*)&sw1[k * C_HID + cb];
        float4 xa = *(const float4*)&sfT[k][rg * 8];
        float4 xb = *(const float4*)&sfT[k][rg * 8 + 4];
        float xr[8] = {xa.x, xa.y, xa.z, xa.w, xb.x, xb.y, xb.z, xb.w};
#pragma unroll
        for (int j = 0; j < 8; j++) {
            acc[j].x = fmaf(w.x, xr[j], acc[j].x);
            acc[j].y = fmaf(w.y, xr[j], acc[j].y);
            acc[j].z = fmaf(w.z, xr[j], acc[j].z);
            acc[j].w = fmaf(w.w, xr[j], acc[j].w);
        }
    }

    float4 s4 = make_float4(0.f, 0.f, 0.f, 0.f), q4 = s4;
#pragma unroll
    for (int j = 0; j < 8; j++) {
        int rr = row0 + rg * 8 + j;
        if (rr < N_PTS) {
            uint2 pk;
            pk.x = f2h2(acc[j].x, acc[j].y);
            pk.y = f2h2(acc[j].z, acc[j].w);
            *(uint2*)&g_x1h[(size_t)rr * C_HID + cb] = pk;
        }
        s4.x += acc[j].x; s4.y += acc[j].y; s4.z += acc[j].z; s4.w += acc[j].w;
        q4.x += acc[j].x * acc[j].x; q4.y += acc[j].y * acc[j].y;
        q4.z += acc[j].z * acc[j].z; q4.w += acc[j].w * acc[j].w;
    }
    *(float4*)&rs[rg][cb] = s4;
    *(float4*)&rq[rg][cb] = q4;
    __syncthreads();
    if (tid < C_HID) {
        float s = 0.f, q = 0.f;
#pragma unroll
        for (int g = 0; g < 8; g++) { s += rs[g][tid]; q += rq[g][tid]; }
        atomicAdd(&g_s1[tid], s);
        atomicAdd(&g_q1[tid], q);
    }
}

// ---- K2: x1 <- relu6(bn1(x1)), fp16, 8 halfs/thread, vector LDS ----
#define TA 256
__global__ void __launch_bounds__(TA) k2_act(const float* __restrict__ gg,
                                             const float* __restrict__ bb) {
    __shared__ __align__(16) float ssc[C_HID], ssh[C_HID];
    int tid = threadIdx.x;
    if (tid < C_HID) {
        float m = g_s1[tid] * (1.0f / N_PTS);
        float v = g_q1[tid] * (1.0f / N_PTS) - m * m;
        float sc = gg[tid] * rsqrtf(v + EPS);
        ssc[tid] = sc;
        ssh[tid] = bb[tid] - m * sc;
    }
    __syncthreads();

    size_t i = (size_t)blockIdx.x * TA + tid;        // uint4 = 8 halfs
    const size_t total = (size_t)N_PTS * C_HID / 8;  // 144/8=18 per row, aligned
    if (i < total) {
        int cb = (int)(i % 18) * 8;
        uint4 u = *(const uint4*)&g_x1h[i * 8];
        float4 scA = *(const float4*)&ssc[cb];
        float4 scB = *(const float4*)&ssc[cb + 4];
        float4 shA = *(const float4*)&ssh[cb];
        float4 shB = *(const float4*)&ssh[cb + 4];
        float scr[8] = {scA.x, scA.y, scA.z, scA.w, scB.x, scB.y, scB.z, scB.w};
        float shr[8] = {shA.x, shA.y, shA.z, shA.w, shB.x, shB.y, shB.z, shB.w};
        unsigned int* up = &u.x;
        uint4 o;
        unsigned int* op = &o.x;
#pragma unroll
        for (int j = 0; j < 4; j++) {
            float2 f = __half22float2(*(__half2*)&up[j]);
            float v0 = relu6f(fmaf(f.x, scr[2 * j],     shr[2 * j]));
            float v1 = relu6f(fmaf(f.y, scr[2 * j + 1], shr[2 * j + 1]));
            op[j] = f2h2(v0, v1);
        }
        *(uint4*)&g_x1h[i * 8] = o;
    }
}

// ---- K3: pure weighted gather conv + BN2 stats (R12 2-channel version) ----
#define R3 64
#define T3 288
__global__ void __launch_bounds__(T3) k3_conv(const float* __restrict__ w2,
                                              const int* __restrict__ in_idx) {
    __shared__ int snbr[R3][KS];
    __shared__ __align__(8) float rs[4][C_HID], rq[4][C_HID];

    int tid = threadIdx.x;
    int row0 = blockIdx.x * R3;

    if (blockIdx.x == 0 && tid < C_OUT) { g_s3[tid] = 0.f; g_q3[tid] = 0.f; }

#pragma unroll
    for (int t = 0; t < 2; t++) {
        int i = tid + t * T3;
        int k = i / R3, r = i % R3;
        int rr = row0 + r;
        snbr[r][k] = (rr < N_PTS) ? in_idx[k * N_PTS + rr] : N_PTS;
    }
    __syncthreads();

    int cg = tid % 72, rl = tid / 72;
    int cb = cg * 2;

    float2 wk[KS];
#pragma unroll
    for (int k = 0; k < KS; k++) wk[k] = *(const float2*)&w2[k * C_HID + cb];

    float s0 = 0.f, s1 = 0.f, q0 = 0.f, q1 = 0.f;
#pragma unroll 2
    for (int j = 0; j < 16; j++) {
        int r = rl * 16 + j;
        unsigned int h[KS];
#pragma unroll
        for (int k = 0; k < KS; k++)
            h[k] = *(const unsigned int*)&g_x1h[snbr[r][k] * C_HID + cb];

        float a0 = 0.f, a1 = 0.f;
#pragma unroll
        for (int k = 0; k < KS; k++) {
            float2 x = __half22float2(*(__half2*)&h[k]);
            a0 = fmaf(wk[k].x, x.x, a0);
            a1 = fmaf(wk[k].y, x.y, a1);
        }
        int rr = row0 + r;
        if (rr < N_PTS) {
            *(unsigned int*)&g_x2h[(size_t)rr * C_HID + cb] = f2h2(a0, a1);
            s0 += a0; q0 += a0 * a0;
            s1 += a1; q1 += a1 * a1;
        }
    }
    rs[rl][cb] = s0; rs[rl][cb + 1] = s1;
    rq[rl][cb] = q0; rq[rl][cb + 1] = q1;
    __syncthreads();
    if (tid < C_HID) {
        float s = rs[0][tid] + rs[1][tid] + rs[2][tid] + rs[3][tid];
        float q = rq[0][tid] + rq[1][tid] + rq[2][tid] + rq[3][tid];
        atomicAdd(&g_s2[tid], s);
        atomicAdd(&g_q2[tid], q);
    }
}

// ---- K5: y = relu6(bn2(x2)) @ w3 via mma.m16n8k16, activation fused ----
// 8 warps/block, 2 m-tiles/warp, R5T=256: same grid (391) & prologue as R12,
// but 2x resident warps and ~half the regs -> better latency hiding.
#define T5 256
#define R5T 256
__global__ void __launch_bounds__(T5) k5_tc(const float* __restrict__ w3,
                                            const float* __restrict__ g2,
                                            const float* __restrict__ b2) {
    __shared__ __align__(4) unsigned int swp[72 * C_OUT];   // half2 (k,k+1) pairs
    __shared__ __align__(8) float ssc[C_HID], ssh[C_HID];
    __shared__ float ssum[C_OUT], ssq[C_OUT];

    int tid = threadIdx.x;
    int lane = tid & 31, wid = tid >> 5;
    int g = lane >> 2, c = lane & 3;

    for (int i = tid; i < 72 * C_OUT; i += T5) {
        int kk = i / C_OUT, n = i % C_OUT;
        swp[i] = f2h2(w3[(2 * kk) * C_OUT + n], w3[(2 * kk + 1) * C_OUT + n]);
    }
    for (int i = tid; i < C_HID; i += T5) {
        float m = g_s2[i] * (1.0f / N_PTS);
        float v = g_q2[i] * (1.0f / N_PTS) - m * m;
        float sc = g2[i] * rsqrtf(v + EPS);
        ssc[i] = sc;
        ssh[i] = b2[i] - m * sc;
    }
    if (tid < C_OUT) { ssum[tid] = 0.f; ssq[tid] = 0.f; }
    __syncthreads();

    int row0 = blockIdx.x * R5T + wid * 32;   // 8 warps x 32 rows = 256

    float acc[2][3][4];
#pragma unroll
    for (int mt = 0; mt < 2; mt++)
#pragma unroll
        for (int nt = 0; nt < 3; nt++)
#pragma unroll
            for (int j = 0; j < 4; j++) acc[mt][nt][j] = 0.f;

#pragma unroll
    for (int ks = 0; ks < 9; ks++) {
        int k0 = ks * 16;
        unsigned int b[3][2];
        int kb = (k0 >> 1) + c;
#pragma unroll
        for (int nt = 0; nt < 3; nt++) {
            int n = nt * 8 + g;
            b[nt][0] = swp[kb * C_OUT + n];
            b[nt][1] = swp[(kb + 4) * C_OUT + n];
        }
        int chL = k0 + 2 * c;
        int chH = chL + 8;
        float2 scL = *(const float2*)&ssc[chL];
        float2 shL = *(const float2*)&ssh[chL];
        float2 scH = *(const float2*)&ssc[chH];
        float2 shH = *(const float2*)&ssh[chH];
#pragma unroll
        for (int mt = 0; mt < 2; mt++) {
            int r  = row0 + mt * 16 + g;
            int rA = min(r, N_PTS - 1);
            int rB = min(r + 8, N_PTS - 1);
            unsigned int a0 = *(const unsigned int*)&g_x2h[(size_t)rA * C_HID + chL];
            unsigned int a1 = *(const unsigned int*)&g_x2h[(size_t)rB * C_HID + chL];
            unsigned int a2 = *(const unsigned int*)&g_x2h[(size_t)rA * C_HID + chH];
            unsigned int a3 = *(const unsigned int*)&g_x2h[(size_t)rB * C_HID + chH];
            float2 f;
            f = __half22float2(*(__half2*)&a0);
            a0 = f2h2(relu6f(fmaf(f.x, scL.x, shL.x)), relu6f(fmaf(f.y, scL.y, shL.y)));
            f = __half22float2(*(__half2*)&a1);
            a1 = f2h2(relu6f(fmaf(f.x, scL.x, shL.x)), relu6f(fmaf(f.y, scL.y, shL.y)));
            f = __half22float2(*(__half2*)&a2);
            a2 = f2h2(relu6f(fmaf(f.x, scH.x, shH.x)), relu6f(fmaf(f.y, scH.y, shH.y)));
            f = __half22float2(*(__half2*)&a3);
            a3 = f2h2(relu6f(fmaf(f.x, scH.x, shH.x)), relu6f(fmaf(f.y, scH.y, shH.y)));
#pragma unroll
            for (int nt = 0; nt < 3; nt++)
                mma16816(acc[mt][nt], a0, a1, a2, a3, b[nt][0], b[nt][1]);
        }
    }

    float s[3][2], q[3][2];
#pragma unroll
    for (int nt = 0; nt < 3; nt++) { s[nt][0] = s[nt][1] = 0.f; q[nt][0] = q[nt][1] = 0.f; }

#pragma unroll
    for (int mt = 0; mt < 2; mt++) {
        int r = row0 + mt * 16 + g;
#pragma unroll
        for (int nt = 0; nt < 3; nt++) {
            int n = nt * 8 + 2 * c;
            if (r < N_PTS) {
                float c0 = acc[mt][nt][0], c1 = acc[mt][nt][1];
                *(float2*)&g_y[(size_t)r * C_OUT + n] = make_float2(c0, c1);
                s[nt][0] += c0; q[nt][0] += c0 * c0;
                s[nt][1] += c1; q[nt][1] += c1 * c1;
            }
            if (r + 8 < N_PTS) {
                float c2 = acc[mt][nt][2], c3 = acc[mt][nt][3];
                *(float2*)&g_y[(size_t)(r + 8) * C_OUT + n] = make_float2(c2, c3);
                s[nt][0] += c2; q[nt][0] += c2 * c2;
                s[nt][1] += c3; q[nt][1] += c3 * c3;
            }
        }
    }
#pragma unroll
    for (int off = 16; off >= 4; off >>= 1) {
#pragma unroll
        for (int nt = 0; nt < 3; nt++) {
#pragma unroll
            for (int j = 0; j < 2; j++) {
                s[nt][j] += __shfl_down_sync(0xffffffffu, s[nt][j], off);
                q[nt][j] += __shfl_down_sync(0xffffffffu, q[nt][j], off);
            }
        }
    }
    if (g == 0) {
#pragma unroll
        for (int nt = 0; nt < 3; nt++) {
            int n = nt * 8 + 2 * c;
            atomicAdd(&ssum[n],     s[nt][0]);
            atomicAdd(&ssum[n + 1], s[nt][1]);
            atomicAdd(&ssq[n],      q[nt][0]);
            atomicAdd(&ssq[n + 1],  q[nt][1]);
        }
    }
    __syncthreads();
    if (tid < C_OUT) {
        atomicAdd(&g_s3[tid], ssum[tid]);
        atomicAdd(&g_q3[tid], ssq[tid]);
    }
}

// ---- K7: out = bn3(y) + feats (float4); block0 zeroes stage-1 accumulators ----
__global__ void k7_out(const float* __restrict__ feats, float* __restrict__ out,
                       const float* __restrict__ g3, const float* __restrict__ b3) {
    __shared__ float ssc[C_OUT], ssh[C_OUT];
    int tid = threadIdx.x;
    if (blockIdx.x == 0 && tid < C_HID) { g_s1[tid] = 0.f; g_q1[tid] = 0.f; }
    if (tid < C_OUT) {
        float m = g_s3[tid] * (1.0f / N_PTS);
        float v = g_q3[tid] * (1.0f / N_PTS) - m * m;
        float sc = g3[tid] * rsqrtf(v + EPS);
        ssc[tid] = sc;
        ssh[tid] = b3[tid] - m * sc;
    }
    __syncthreads();

    int i = blockIdx.x * blockDim.x + tid;   // float4 index
    if (i < N_PTS * C_OUT / 4) {
        int cb = (i % 6) * 4;
        float4 y  = *(const float4*)&g_y[i * 4];
        float4 f  = *(const float4*)&feats[i * 4];
        float4 o;
        o.x = fmaf(y.x, ssc[cb + 0], ssh[cb + 0]) + f.x;
        o.y = fmaf(y.y, ssc[cb + 1], ssh[cb + 1]) + f.y;
        o.z = fmaf(y.z, ssc[cb + 2], ssh[cb + 2]) + f.z;
        o.w = fmaf(y.w, ssc[cb + 3], ssh[cb + 3]) + f.w;
        *(float4*)&out[i * 4] = o;
    }
}

extern "C" void kernel_launch(void* const* d_in, const int* in_sizes, int n_in,
                              void* d_out, int out_size) {
    const float* feats = (const float*)d_in[0];
    const float* w1    = (const float*)d_in[1];
    const float* g1    = (const float*)d_in[2];
    const float* b1    = (const float*)d_in[3];
    const float* w2    = (const float*)d_in[4];
    const float* g2    = (const float*)d_in[5];
    const float* b2    = (const float*)d_in[6];
    const float* w3    = (const float*)d_in[7];
    const float* g3    = (const float*)d_in[8];
    const float* b3    = (const float*)d_in[9];
    const int*   in_idx = (const int*)d_in[10];
    float* out = (float*)d_out;

    int nb1 = (N_PTS + R1 - 1) / R1;
    k1_gemm1<<<nb1, T1>>>(feats, w1);

    unsigned nba = (unsigned)(((size_t)N_PTS * C_HID / 8 + TA - 1) / TA);
    k2_act<<<nba, TA>>>(g1, b1);

    int nb3 = (N_PTS + R3 - 1) / R3;
    k3_conv<<<nb3, T3>>>(w2, in_idx);

    int nb5 = (N_PTS + R5T - 1) / R5T;
    k5_tc<<<nb5, T5>>>(w3, g2, b2);

    int total4 = N_PTS * C_OUT / 4;
    k7_out<<<(total4 + 255) / 256, 256>>>(feats, out, g3, b3);
}

// round 16
// speedup vs baseline: 1.1506x; 1.0254x over previous
#include <cuda_runtime.h>
#include <cuda_fp16.h>

#define N_PTS 100000
#define C_IN 24
#define C_HID 144
#define C_OUT 24
#define KS 9
#define EPS 1e-5f

// ---- scratch (device globals: allocation-free rule) ----
__device__ __align__(16) __half g_x1h[(N_PTS + 1) * C_HID];
__device__ __align__(16) __half g_x2h[N_PTS * C_HID];
__device__ __align__(16) float  g_y [N_PTS * C_OUT];

__device__ float g_s1[C_HID], g_q1[C_HID];
__device__ float g_s2[C_HID], g_q2[C_HID];
__device__ float g_s3[C_OUT], g_q3[C_OUT];

__device__ __forceinline__ float relu6f(float x) { return fminf(fmaxf(x, 0.f), 6.f); }

// PDL primitives (sm_90+): dependents launch early; wait gates predecessor reads.
__device__ __forceinline__ void gdc_wait() {
    asm volatile("griddepcontrol.wait;" ::: "memory");
}
__device__ __forceinline__ void gdc_launch() {
    asm volatile("griddepcontrol.launch_dependents;");
}

__device__ __forceinline__ void mma16816(float* d,
                                         unsigned a0, unsigned a1, unsigned a2, unsigned a3,
                                         unsigned b0, unsigned b1) {
    asm volatile("mma.sync.aligned.m16n8k16.row.col.f32.f16.f16.f32 "
                 "{%0,%1,%2,%3}, {%4,%5,%6,%7}, {%8,%9}, {%0,%1,%2,%3};\n"
                 : "+f"(d[0]), "+f"(d[1]), "+f"(d[2]), "+f"(d[3])
                 : "r"(a0), "r"(a1), "r"(a2), "r"(a3), "r"(b0), "r"(b1));
}

__device__ __forceinline__ unsigned f2h2(float a, float b) {
    __half2 h = __floats2half2_rn(a, b);
    return *(unsigned*)&h;
}

// ---- K1: x1 = feats @ w1 (scalar fp32, fp16 out); block0 zeroes stage-2 accums ----
#define R1 64
#define T1 288
__global__ void __launch_bounds__(T1) k1_gemm1(const float* __restrict__ feats,
                                               const float* __restrict__ w1) {
    __shared__ __align__(16) float sfT[C_IN][R1];
    __shared__ __align__(16) float sw1[C_IN * C_HID];
    __shared__ __align__(16) float rs[8][C_HID], rq[8][C_HID];

    int tid = threadIdx.x;
    int row0 = blockIdx.x * R1;

    if (blockIdx.x == 0 && tid < C_HID) { g_s2[tid] = 0.f; g_q2[tid] = 0.f; }

    for (int i = tid; i < C_IN * C_HID; i += T1) sw1[i] = w1[i];
    for (int i = tid; i < R1 * C_IN; i += T1) {
        int r = i / C_IN, k = i % C_IN;
        int rr = row0 + r;
        sfT[k][r] = (rr < N_PTS) ? feats[rr * C_IN + k] : 0.f;
    }
    __syncthreads();

    int c4 = tid % 36, rg = tid / 36;
    int cb = c4 * 4;
    float4 acc[8];
#pragma unroll
    for (int j = 0; j < 8; j++) acc[j] = make_float4(0.f, 0.f, 0.f, 0.f);

#pragma unroll
    for (int k = 0; k < C_IN; k++) {
        float4 w  = *(const float4*)&sw1[k * C_HID + cb];
        float4 xa = *(const float4*)&sfT[k][rg * 8];
        float4 xb = *(const float4*)&sfT[k][rg * 8 + 4];
        float xr[8] = {xa.x, xa.y, xa.z, xa.w, xb.x, xb.y, xb.z, xb.w};
#pragma unroll
        for (int j = 0; j < 8; j++) {
            acc[j].x = fmaf(w.x, xr[j], acc[j].x);
            acc[j].y = fmaf(w.y, xr[j], acc[j].y);
            acc[j].z = fmaf(w.z, xr[j], acc[j].z);
            acc[j].w = fmaf(w.w, xr[j], acc[j].w);
        }
    }

    float4 s4 = make_float4(0.f, 0.f, 0.f, 0.f), q4 = s4;
#pragma unroll
    for (int j = 0; j < 8; j++) {
        int rr = row0 + rg * 8 + j;
        if (rr < N_PTS) {
            uint2 pk;
            pk.x = f2h2(acc[j].x, acc[j].y);
            pk.y = f2h2(acc[j].z, acc[j].w);
            *(uint2*)&g_x1h[(size_t)rr * C_HID + cb] = pk;
        }
        s4.x += acc[j].x; s4.y += acc[j].y; s4.z += acc[j].z; s4.w += acc[j].w;
        q4.x += acc[j].x * acc[j].x; q4.y += acc[j].y * acc[j].y;
        q4.z += acc[j].z * acc[j].z; q4.w += acc[j].w * acc[j].w;
    }
    *(float4*)&rs[rg][cb] = s4;
    *(float4*)&rq[rg][cb] = q4;
    __syncthreads();
    if (tid < C_HID) {
        float s = 0.f, q = 0.f;
#pragma unroll
        for (int g = 0; g < 8; g++) { s += rs[g][tid]; q += rq[g][tid]; }
        atomicAdd(&g_s1[tid], s);
        atomicAdd(&g_q1[tid], q);
    }
    gdc_launch();
}

// ---- K2: x1 <- relu6(bn1(x1)), fp16, 8 halfs/thread, vector LDS ----
#define TA 256
__global__ void __launch_bounds__(TA) k2_act(const float* __restrict__ gg,
                                             const float* __restrict__ bb) {
    __shared__ __align__(16) float ssc[C_HID], ssh[C_HID];
    int tid = threadIdx.x;
    gdc_wait();                      // needs g_s1/g_q1 + g_x1h from k1
    if (tid < C_HID) {
        float m = g_s1[tid] * (1.0f / N_PTS);
        float v = g_q1[tid] * (1.0f / N_PTS) - m * m;
        float sc = gg[tid] * rsqrtf(v + EPS);
        ssc[tid] = sc;
        ssh[tid] = bb[tid] - m * sc;
    }
    __syncthreads();

    size_t i = (size_t)blockIdx.x * TA + tid;        // uint4 = 8 halfs
    const size_t total = (size_t)N_PTS * C_HID / 8;  // 144/8=18 per row, aligned
    if (i < total) {
        int cb = (int)(i % 18) * 8;
        uint4 u = *(const uint4*)&g_x1h[i * 8];
        float4 scA = *(const float4*)&ssc[cb];
        float4 scB = *(const float4*)&ssc[cb + 4];
        float4 shA = *(const float4*)&ssh[cb];
        float4 shB = *(const float4*)&ssh[cb + 4];
        float scr[8] = {scA.x, scA.y, scA.z, scA.w, scB.x, scB.y, scB.z, scB.w};
        float shr[8] = {shA.x, shA.y, shA.z, shA.w, shB.x, shB.y, shB.z, shB.w};
        unsigned int* up = &u.x;
        uint4 o;
        unsigned int* op = &o.x;
#pragma unroll
        for (int j = 0; j < 4; j++) {
            float2 f = __half22float2(*(__half2*)&up[j]);
            float v0 = relu6f(fmaf(f.x, scr[2 * j],     shr[2 * j]));
            float v1 = relu6f(fmaf(f.y, scr[2 * j + 1], shr[2 * j + 1]));
            op[j] = f2h2(v0, v1);
        }
        *(uint4*)&g_x1h[i * 8] = o;
    }
    gdc_launch();
}

// ---- K3: pure weighted gather conv + BN2 stats ----
#define R3 64
#define T3 288
__global__ void __launch_bounds__(T3) k3_conv(const float* __restrict__ w2,
                                              const int* __restrict__ in_idx) {
    __shared__ int snbr[R3][KS];
    __shared__ __align__(8) float rs[4][C_HID], rq[4][C_HID];

    int tid = threadIdx.x;
    int row0 = blockIdx.x * R3;

    if (blockIdx.x == 0 && tid < C_OUT) { g_s3[tid] = 0.f; g_q3[tid] = 0.f; }

    // prologue reads only harness inputs (in_idx, w2) -> runs before gdc_wait
#pragma unroll
    for (int t = 0; t < 2; t++) {
        int i = tid + t * T3;
        int k = i / R3, r = i % R3;
        int rr = row0 + r;
        snbr[r][k] = (rr < N_PTS) ? in_idx[k * N_PTS + rr] : N_PTS;
    }

    int cg = tid % 72, rl = tid / 72;
    int cb = cg * 2;

    float2 wk[KS];
#pragma unroll
    for (int k = 0; k < KS; k++) wk[k] = *(const float2*)&w2[k * C_HID + cb];

    gdc_wait();                      // needs g_x1h (activated) from k2
    __syncthreads();

    float s0 = 0.f, s1 = 0.f, q0 = 0.f, q1 = 0.f;
#pragma unroll 2
    for (int j = 0; j < 16; j++) {
        int r = rl * 16 + j;
        unsigned int h[KS];
#pragma unroll
        for (int k = 0; k < KS; k++)
            h[k] = *(const unsigned int*)&g_x1h[snbr[r][k] * C_HID + cb];

        float a0 = 0.f, a1 = 0.f;
#pragma unroll
        for (int k = 0; k < KS; k++) {
            float2 x = __half22float2(*(__half2*)&h[k]);
            a0 = fmaf(wk[k].x, x.x, a0);
            a1 = fmaf(wk[k].y, x.y, a1);
        }
        int rr = row0 + r;
        if (rr < N_PTS) {
            *(unsigned int*)&g_x2h[(size_t)rr * C_HID + cb] = f2h2(a0, a1);
            s0 += a0; q0 += a0 * a0;
            s1 += a1; q1 += a1 * a1;
        }
    }
    rs[rl][cb] = s0; rs[rl][cb + 1] = s1;
    rq[rl][cb] = q0; rq[rl][cb + 1] = q1;
    __syncthreads();
    if (tid < C_HID) {
        float s = rs[0][tid] + rs[1][tid] + rs[2][tid] + rs[3][tid];
        float q = rq[0][tid] + rq[1][tid] + rq[2][tid] + rq[3][tid];
        atomicAdd(&g_s2[tid], s);
        atomicAdd(&g_q2[tid], q);
    }
    gdc_launch();
}

// ---- K5: y = relu6(bn2(x2)) @ w3 via mma.m16n8k16, activation fused; 8 warps ----
#define T5 256
#define R5T 256
__global__ void __launch_bounds__(T5) k5_tc(const float* __restrict__ w3,
                                            const float* __restrict__ g2,
                                            const float* __restrict__ b2) {
    __shared__ __align__(4) unsigned int swp[72 * C_OUT];   // half2 (k,k+1) pairs
    __shared__ __align__(8) float ssc[C_HID], ssh[C_HID];
    __shared__ float ssum[C_OUT], ssq[C_OUT];

    int tid = threadIdx.x;
    int lane = tid & 31, wid = tid >> 5;
    int g = lane >> 2, c = lane & 3;

    // prologue: pack w3 (harness input) before waiting on k3
    for (int i = tid; i < 72 * C_OUT; i += T5) {
        int kk = i / C_OUT, n = i % C_OUT;
        swp[i] = f2h2(w3[(2 * kk) * C_OUT + n], w3[(2 * kk + 1) * C_OUT + n]);
    }
    if (tid < C_OUT) { ssum[tid] = 0.f; ssq[tid] = 0.f; }

    gdc_wait();                      // needs g_s2/g_q2 + g_x2h from k3
    for (int i = tid; i < C_HID; i += T5) {
        float m = g_s2[i] * (1.0f / N_PTS);
        float v = g_q2[i] * (1.0f / N_PTS) - m * m;
        float sc = g2[i] * rsqrtf(v + EPS);
        ssc[i] = sc;
        ssh[i] = b2[i] - m * sc;
    }
    __syncthreads();

    int row0 = blockIdx.x * R5T + wid * 32;   // 8 warps x 32 rows = 256

    float acc[2][3][4];
#pragma unroll
    for (int mt = 0; mt < 2; mt++)
#pragma unroll
        for (int nt = 0; nt < 3; nt++)
#pragma unroll
            for (int j = 0; j < 4; j++) acc[mt][nt][j] = 0.f;

#pragma unroll
    for (int ks = 0; ks < 9; ks++) {
        int k0 = ks * 16;
        unsigned int b[3][2];
        int kb = (k0 >> 1) + c;
#pragma unroll
        for (int nt = 0; nt < 3; nt++) {
            int n = nt * 8 + g;
            b[nt][0] = swp[kb * C_OUT + n];
            b[nt][1] = swp[(kb + 4) * C_OUT + n];
        }
        int chL = k0 + 2 * c;
        int chH = chL + 8;
        float2 scL = *(const float2*)&ssc[chL];
        float2 shL = *(const float2*)&ssh[chL];
        float2 scH = *(const float2*)&ssc[chH];
        float2 shH = *(const float2*)&ssh[chH];
#pragma unroll
        for (int mt = 0; mt < 2; mt++) {
            int r  = row0 + mt * 16 + g;
            int rA = min(r, N_PTS - 1);
            int rB = min(r + 8, N_PTS - 1);
            unsigned int a0 = *(const unsigned int*)&g_x2h[(size_t)rA * C_HID + chL];
            unsigned int a1 = *(const unsigned int*)&g_x2h[(size_t)rB * C_HID + chL];
            unsigned int a2 = *(const unsigned int*)&g_x2h[(size_t)rA * C_HID + chH];
            unsigned int a3 = *(const unsigned int*)&g_x2h[(size_t)rB * C_HID + chH];
            float2 f;
            f = __half22float2(*(__half2*)&a0);
            a0 = f2h2(relu6f(fmaf(f.x, scL.x, shL.x)), relu6f(fmaf(f.y, scL.y, shL.y)));
            f = __half22float2(*(__half2*)&a1);
            a1 = f2h2(relu6f(fmaf(f.x, scL.x, shL.x)), relu6f(fmaf(f.y, scL.y, shL.y)));
            f = __half22float2(*(__half2*)&a2);
            a2 = f2h2(relu6f(fmaf(f.x, scH.x, shH.x)), relu6f(fmaf(f.y, scH.y, shH.y)));
            f = __half22float2(*(__half2*)&a3);
            a3 = f2h2(relu6f(fmaf(f.x, scH.x, shH.x)), relu6f(fmaf(f.y, scH.y, shH.y)));
#pragma unroll
            for (int nt = 0; nt < 3; nt++)
                mma16816(acc[mt][nt], a0, a1, a2, a3, b[nt][0], b[nt][1]);
        }
    }

    float s[3][2], q[3][2];
#pragma unroll
    for (int nt = 0; nt < 3; nt++) { s[nt][0] = s[nt][1] = 0.f; q[nt][0] = q[nt][1] = 0.f; }

#pragma unroll
    for (int mt = 0; mt < 2; mt++) {
        int r = row0 + mt * 16 + g;
#pragma unroll
        for (int nt = 0; nt < 3; nt++) {
            int n = nt * 8 + 2 * c;
            if (r < N_PTS) {
                float c0 = acc[mt][nt][0], c1 = acc[mt][nt][1];
                *(float2*)&g_y[(size_t)r * C_OUT + n] = make_float2(c0, c1);
                s[nt][0] += c0; q[nt][0] += c0 * c0;
                s[nt][1] += c1; q[nt][1] += c1 * c1;
            }
            if (r + 8 < N_PTS) {
                float c2 = acc[mt][nt][2], c3 = acc[mt][nt][3];
                *(float2*)&g_y[(size_t)(r + 8) * C_OUT + n] = make_float2(c2, c3);
                s[nt][0] += c2; q[nt][0] += c2 * c2;
                s[nt][1] += c3; q[nt][1] += c3 * c3;
            }
        }
    }
#pragma unroll
    for (int off = 16; off >= 4; off >>= 1) {
#pragma unroll
        for (int nt = 0; nt < 3; nt++) {
#pragma unroll
            for (int j = 0; j < 2; j++) {
                s[nt][j] += __shfl_down_sync(0xffffffffu, s[nt][j], off);
                q[nt][j] += __shfl_down_sync(0xffffffffu, q[nt][j], off);
            }
        }
    }
    if (g == 0) {
#pragma unroll
        for (int nt = 0; nt < 3; nt++) {
            int n = nt * 8 + 2 * c;
            atomicAdd(&ssum[n],     s[nt][0]);
            atomicAdd(&ssum[n + 1], s[nt][1]);
            atomicAdd(&ssq[n],      q[nt][0]);
            atomicAdd(&ssq[n + 1],  q[nt][1]);
        }
    }
    __syncthreads();
    if (tid < C_OUT) {
        atomicAdd(&g_s3[tid], ssum[tid]);
        atomicAdd(&g_q3[tid], ssq[tid]);
    }
    gdc_launch();
}

// ---- K7: out = bn3(y) + feats (float4); block0 zeroes stage-1 accumulators ----
__global__ void k7_out(const float* __restrict__ feats, float* __restrict__ out,
                       const float* __restrict__ g3, const float* __restrict__ b3) {
    __shared__ float ssc[C_OUT], ssh[C_OUT];
    int tid = threadIdx.x;
    gdc_wait();                      // needs g_s3/g_q3 + g_y from k5
    if (blockIdx.x == 0 && tid < C_HID) { g_s1[tid] = 0.f; g_q1[tid] = 0.f; }
    if (tid < C_OUT) {
        float m = g_s3[tid] * (1.0f / N_PTS);
        float v = g_q3[tid] * (1.0f / N_PTS) - m * m;
        float sc = g3[tid] * rsqrtf(v + EPS);
        ssc[tid] = sc;
        ssh[tid] = b3[tid] - m * sc;
    }
    __syncthreads();

    int i = blockIdx.x * blockDim.x + tid;   // float4 index
    if (i < N_PTS * C_OUT / 4) {
        int cb = (i % 6) * 4;
        float4 y  = *(const float4*)&g_y[i * 4];
        float4 f  = *(const float4*)&feats[i * 4];
        float4 o;
        o.x = fmaf(y.x, ssc[cb + 0], ssh[cb + 0]) + f.x;
        o.y = fmaf(y.y, ssc[cb + 1], ssh[cb + 1]) + f.y;
        o.z = fmaf(y.z, ssc[cb + 2], ssh[cb + 2]) + f.z;
        o.w = fmaf(y.w, ssc[cb + 3], ssh[cb + 3]) + f.w;
        *(float4*)&out[i * 4] = o;
    }
}

// ---- PDL launch helper ----
template <typename... Args>
static void launch_pdl(void (*kern)(Args...), dim3 grid, dim3 block, Args... args) {
    cudaLaunchConfig_t cfg = {};
    cfg.gridDim = grid;
    cfg.blockDim = block;
    cfg.dynamicSmemBytes = 0;
    cfg.stream = 0;
    cudaLaunchAttribute attr[1];
    attr[0].id = cudaLaunchAttributeProgrammaticStreamSerialization;
    attr[0].val.programmaticStreamSerializationAllowed = 1;
    cfg.attrs = attr;
    cfg.numAttrs = 1;
    cudaLaunchKernelEx(&cfg, kern, args...);
}

extern "C" void kernel_launch(void* const* d_in, const int* in_sizes, int n_in,
                              void* d_out, int out_size) {
    const float* feats = (const float*)d_in[0];
    const float* w1    = (const float*)d_in[1];
    const float* g1    = (const float*)d_in[2];
    const float* b1    = (const float*)d_in[3];
    const float* w2    = (const float*)d_in[4];
    const float* g2    = (const float*)d_in[5];
    const float* b2    = (const float*)d_in[6];
    const float* w3    = (const float*)d_in[7];
    const float* g3    = (const float*)d_in[8];
    const float* b3    = (const float*)d_in[9];
    const int*   in_idx = (const int*)d_in[10];
    float* out = (float*)d_out;

    int nb1 = (N_PTS + R1 - 1) / R1;
    k1_gemm1<<<nb1, T1>>>(feats, w1);

    unsigned nba = (unsigned)(((size_t)N_PTS * C_HID / 8 + TA - 1) / TA);
    launch_pdl(k2_act, dim3(nba), dim3(TA), g1, b1);

    int nb3 = (N_PTS + R3 - 1) / R3;
    launch_pdl(k3_conv, dim3(nb3), dim3(T3), w2, in_idx);

    int nb5 = (N_PTS + R5T - 1) / R5T;
    launch_pdl(k5_tc, dim3(nb5), dim3(T5), w3, g2, b2);

    int total4 = N_PTS * C_OUT / 4;
    launch_pdl(k7_out, dim3((total4 + 255) / 256), dim3(256), feats, out, g3, b3);
}

// round 17
// speedup vs baseline: 1.2040x; 1.0465x over previous
#include <cuda_runtime.h>
#include <cuda_fp16.h>

#define N_PTS 100000
#define C_IN 24
#define C_HID 144
#define C_OUT 24
#define KS 9
#define EPS 1e-5f

// ---- scratch (device globals: allocation-free rule) ----
__device__ __align__(16) __half g_x1h[(N_PTS + 1) * C_HID];
__device__ __align__(16) __half g_x2h[N_PTS * C_HID];
__device__ __align__(16) __half g_yh [N_PTS * C_OUT];

__device__ float g_s1[C_HID], g_q1[C_HID];
__device__ float g_s2[C_HID], g_q2[C_HID];
__device__ float g_s3[C_OUT], g_q3[C_OUT];

__device__ __forceinline__ float relu6f(float x) { return fminf(fmaxf(x, 0.f), 6.f); }

// PDL primitives (sm_90+)
__device__ __forceinline__ void gdc_wait() {
    asm volatile("griddepcontrol.wait;" ::: "memory");
}
__device__ __forceinline__ void gdc_launch() {
    asm volatile("griddepcontrol.launch_dependents;");
}

__device__ __forceinline__ void mma16816(float* d,
                                         unsigned a0, unsigned a1, unsigned a2, unsigned a3,
                                         unsigned b0, unsigned b1) {
    asm volatile("mma.sync.aligned.m16n8k16.row.col.f32.f16.f16.f32 "
                 "{%0,%1,%2,%3}, {%4,%5,%6,%7}, {%8,%9}, {%0,%1,%2,%3};\n"
                 : "+f"(d[0]), "+f"(d[1]), "+f"(d[2]), "+f"(d[3])
                 : "r"(a0), "r"(a1), "r"(a2), "r"(a3), "r"(b0), "r"(b1));
}

__device__ __forceinline__ unsigned f2h2(float a, float b) {
    __half2 h = __floats2half2_rn(a, b);
    return *(unsigned*)&h;
}

// ---- K1: x1 = feats @ w1 (scalar fp32, fp16 out); block0 zeroes stage-2 accums ----
#define R1 64
#define T1 288
__global__ void __launch_bounds__(T1) k1_gemm1(const float* __restrict__ feats,
                                               const float* __restrict__ w1) {
    __shared__ __align__(16) float sfT[C_IN][R1];
    __shared__ __align__(16) float sw1[C_IN * C_HID];
    __shared__ __align__(16) float rs[8][C_HID], rq[8][C_HID];

    int tid = threadIdx.x;
    int row0 = blockIdx.x * R1;

    if (blockIdx.x == 0 && tid < C_HID) { g_s2[tid] = 0.f; g_q2[tid] = 0.f; }

    for (int i = tid; i < C_IN * C_HID; i += T1) sw1[i] = w1[i];
    for (int i = tid; i < R1 * C_IN; i += T1) {
        int r = i / C_IN, k = i % C_IN;
        int rr = row0 + r;
        sfT[k][r] = (rr < N_PTS) ? feats[rr * C_IN + k] : 0.f;
    }
    __syncthreads();

    int c4 = tid % 36, rg = tid / 36;
    int cb = c4 * 4;
    float4 acc[8];
#pragma unroll
    for (int j = 0; j < 8; j++) acc[j] = make_float4(0.f, 0.f, 0.f, 0.f);

#pragma unroll
    for (int k = 0; k < C_IN; k++) {
        float4 w  = *(const float4*)&sw1[k * C_HID + cb];
        float4 xa = *(const float4*)&sfT[k][rg * 8];
        float4 xb = *(const float4*)&sfT[k][rg * 8 + 4];
        float xr[8] = {xa.x, xa.y, xa.z, xa.w, xb.x, xb.y, xb.z, xb.w};
#pragma unroll
        for (int j = 0; j < 8; j++) {
            acc[j].x = fmaf(w.x, xr[j], acc[j].x);
            acc[j].y = fmaf(w.y, xr[j], acc[j].y);
            acc[j].z = fmaf(w.z, xr[j], acc[j].z);
            acc[j].w = fmaf(w.w, xr[j], acc[j].w);
        }
    }

    float4 s4 = make_float4(0.f, 0.f, 0.f, 0.f), q4 = s4;
#pragma unroll
    for (int j = 0; j < 8; j++) {
        int rr = row0 + rg * 8 + j;
        if (rr < N_PTS) {
            uint2 pk;
            pk.x = f2h2(acc[j].x, acc[j].y);
            pk.y = f2h2(acc[j].z, acc[j].w);
            *(uint2*)&g_x1h[(size_t)rr * C_HID + cb] = pk;
        }
        s4.x += acc[j].x; s4.y += acc[j].y; s4.z += acc[j].z; s4.w += acc[j].w;
        q4.x += acc[j].x * acc[j].x; q4.y += acc[j].y * acc[j].y;
        q4.z += acc[j].z * acc[j].z; q4.w += acc[j].w * acc[j].w;
    }
    *(float4*)&rs[rg][cb] = s4;
    *(float4*)&rq[rg][cb] = q4;
    __syncthreads();
    if (tid < C_HID) {
        float s = 0.f, q = 0.f;
#pragma unroll
        for (int g = 0; g < 8; g++) { s += rs[g][tid]; q += rq[g][tid]; }
        atomicAdd(&g_s1[tid], s);
        atomicAdd(&g_q1[tid], q);
    }
    gdc_launch();
}

// ---- K2: x1 <- relu6(bn1(x1)), fp16, 8 halfs/thread, vector LDS ----
#define TA 256
__global__ void __launch_bounds__(TA) k2_act(const float* __restrict__ gg,
                                             const float* __restrict__ bb) {
    __shared__ __align__(16) float ssc[C_HID], ssh[C_HID];
    int tid = threadIdx.x;
    gdc_wait();
    if (tid < C_HID) {
        float m = g_s1[tid] * (1.0f / N_PTS);
        float v = g_q1[tid] * (1.0f / N_PTS) - m * m;
        float sc = gg[tid] * rsqrtf(v + EPS);
        ssc[tid] = sc;
        ssh[tid] = bb[tid] - m * sc;
    }
    __syncthreads();

    size_t i = (size_t)blockIdx.x * TA + tid;        // uint4 = 8 halfs
    const size_t total = (size_t)N_PTS * C_HID / 8;
    if (i < total) {
        int cb = (int)(i % 18) * 8;
        uint4 u = *(const uint4*)&g_x1h[i * 8];
        float4 scA = *(const float4*)&ssc[cb];
        float4 scB = *(const float4*)&ssc[cb + 4];
        float4 shA = *(const float4*)&ssh[cb];
        float4 shB = *(const float4*)&ssh[cb + 4];
        float scr[8] = {scA.x, scA.y, scA.z, scA.w, scB.x, scB.y, scB.z, scB.w};
        float shr[8] = {shA.x, shA.y, shA.z, shA.w, shB.x, shB.y, shB.z, shB.w};
        unsigned int* up = &u.x;
        uint4 o;
        unsigned int* op = &o.x;
#pragma unroll
        for (int j = 0; j < 4; j++) {
            float2 f = __half22float2(*(__half2*)&up[j]);
            float v0 = relu6f(fmaf(f.x, scr[2 * j],     shr[2 * j]));
            float v1 = relu6f(fmaf(f.y, scr[2 * j + 1], shr[2 * j + 1]));
            op[j] = f2h2(v0, v1);
        }
        *(uint4*)&g_x1h[i * 8] = o;
    }
    gdc_launch();
}

// ---- K3: pure weighted gather conv + BN2 stats ----
// smem holds element OFFSETS (nbr*C_HID): no IMAD in the gather dependency chain.
// unroll 4 -> 36 outstanding gathers per thread.
#define R3 64
#define T3 288
__global__ void __launch_bounds__(T3) k3_conv(const float* __restrict__ w2,
                                              const int* __restrict__ in_idx) {
    __shared__ int soff[R3][KS];               // nbr * C_HID
    __shared__ __align__(8) float rs[4][C_HID], rq[4][C_HID];

    int tid = threadIdx.x;
    int row0 = blockIdx.x * R3;

    if (blockIdx.x == 0 && tid < C_OUT) { g_s3[tid] = 0.f; g_q3[tid] = 0.f; }

    // prologue reads only harness inputs (in_idx, w2) -> before gdc_wait
#pragma unroll
    for (int t = 0; t < 2; t++) {
        int i = tid + t * T3;
        int k = i / R3, r = i % R3;
        int rr = row0 + r;
        int nbr = (rr < N_PTS) ? in_idx[k * N_PTS + rr] : N_PTS;
        soff[r][k] = nbr * C_HID;
    }

    int cg = tid % 72, rl = tid / 72;
    int cb = cg * 2;

    float2 wk[KS];
#pragma unroll
    for (int k = 0; k < KS; k++) wk[k] = *(const float2*)&w2[k * C_HID + cb];

    gdc_wait();                      // needs g_x1h (activated) from k2
    __syncthreads();

    const __half* x1p = &g_x1h[cb];

    float s0 = 0.f, s1 = 0.f, q0 = 0.f, q1 = 0.f;
#pragma unroll 4
    for (int j = 0; j < 16; j++) {
        int r = rl * 16 + j;
        unsigned int h[KS];
#pragma unroll
        for (int k = 0; k < KS; k++)
            h[k] = *(const unsigned int*)&x1p[soff[r][k]];

        float a0 = 0.f, a1 = 0.f;
#pragma unroll
        for (int k = 0; k < KS; k++) {
            float2 x = __half22float2(*(__half2*)&h[k]);
            a0 = fmaf(wk[k].x, x.x, a0);
            a1 = fmaf(wk[k].y, x.y, a1);
        }
        int rr = row0 + r;
        if (rr < N_PTS) {
            *(unsigned int*)&g_x2h[(size_t)rr * C_HID + cb] = f2h2(a0, a1);
            s0 += a0; q0 += a0 * a0;
            s1 += a1; q1 += a1 * a1;
        }
    }
    rs[rl][cb] = s0; rs[rl][cb + 1] = s1;
    rq[rl][cb] = q0; rq[rl][cb + 1] = q1;
    __syncthreads();
    if (tid < C_HID) {
        float s = rs[0][tid] + rs[1][tid] + rs[2][tid] + rs[3][tid];
        float q = rq[0][tid] + rq[1][tid] + rq[2][tid] + rq[3][tid];
        atomicAdd(&g_s2[tid], s);
        atomicAdd(&g_q2[tid], q);
    }
    gdc_launch();
}

// ---- K5: y(fp16) = relu6(bn2(x2)) @ w3 via mma.m16n8k16, activation fused; 8 warps ----
#define T5 256
#define R5T 256
__global__ void __launch_bounds__(T5) k5_tc(const float* __restrict__ w3,
                                            const float* __restrict__ g2,
                                            const float* __restrict__ b2) {
    __shared__ __align__(4) unsigned int swp[72 * C_OUT];
    __shared__ __align__(8) float ssc[C_HID], ssh[C_HID];
    __shared__ float ssum[C_OUT], ssq[C_OUT];

    int tid = threadIdx.x;
    int lane = tid & 31, wid = tid >> 5;
    int g = lane >> 2, c = lane & 3;

    for (int i = tid; i < 72 * C_OUT; i += T5) {
        int kk = i / C_OUT, n = i % C_OUT;
        swp[i] = f2h2(w3[(2 * kk) * C_OUT + n], w3[(2 * kk + 1) * C_OUT + n]);
    }
    if (tid < C_OUT) { ssum[tid] = 0.f; ssq[tid] = 0.f; }

    gdc_wait();
    for (int i = tid; i < C_HID; i += T5) {
        float m = g_s2[i] * (1.0f / N_PTS);
        float v = g_q2[i] * (1.0f / N_PTS) - m * m;
        float sc = g2[i] * rsqrtf(v + EPS);
        ssc[i] = sc;
        ssh[i] = b2[i] - m * sc;
    }
    __syncthreads();

    int row0 = blockIdx.x * R5T + wid * 32;

    float acc[2][3][4];
#pragma unroll
    for (int mt = 0; mt < 2; mt++)
#pragma unroll
        for (int nt = 0; nt < 3; nt++)
#pragma unroll
            for (int j = 0; j < 4; j++) acc[mt][nt][j] = 0.f;

#pragma unroll
    for (int ks = 0; ks < 9; ks++) {
        int k0 = ks * 16;
        unsigned int b[3][2];
        int kb = (k0 >> 1) + c;
#pragma unroll
        for (int nt = 0; nt < 3; nt++) {
            int n = nt * 8 + g;
            b[nt][0] = swp[kb * C_OUT + n];
            b[nt][1] = swp[(kb + 4) * C_OUT + n];
        }
        int chL = k0 + 2 * c;
        int chH = chL + 8;
        float2 scL = *(const float2*)&ssc[chL];
        float2 shL = *(const float2*)&ssh[chL];
        float2 scH = *(const float2*)&ssc[chH];
        float2 shH = *(const float2*)&ssh[chH];
#pragma unroll
        for (int mt = 0; mt < 2; mt++) {
            int r  = row0 + mt * 16 + g;
            int rA = min(r, N_PTS - 1);
            int rB = min(r + 8, N_PTS - 1);
            unsigned int a0 = *(const unsigned int*)&g_x2h[(size_t)rA * C_HID + chL];
            unsigned int a1 = *(const unsigned int*)&g_x2h[(size_t)rB * C_HID + chL];
            unsigned int a2 = *(const unsigned int*)&g_x2h[(size_t)rA * C_HID + chH];
            unsigned int a3 = *(const unsigned int*)&g_x2h[(size_t)rB * C_HID + chH];
            float2 f;
            f = __half22float2(*(__half2*)&a0);
            a0 = f2h2(relu6f(fmaf(f.x, scL.x, shL.x)), relu6f(fmaf(f.y, scL.y, shL.y)));
            f = __half22float2(*(__half2*)&a1);
            a1 = f2h2(relu6f(fmaf(f.x, scL.x, shL.x)), relu6f(fmaf(f.y, scL.y, shL.y)));
            f = __half22float2(*(__half2*)&a2);
            a2 = f2h2(relu6f(fmaf(f.x, scH.x, shH.x)), relu6f(fmaf(f.y, scH.y, shH.y)));
            f = __half22float2(*(__half2*)&a3);
            a3 = f2h2(relu6f(fmaf(f.x, scH.x, shH.x)), relu6f(fmaf(f.y, scH.y, shH.y)));
#pragma unroll
            for (int nt = 0; nt < 3; nt++)
                mma16816(acc[mt][nt], a0, a1, a2, a3, b[nt][0], b[nt][1]);
        }
    }

    float s[3][2], q[3][2];
#pragma unroll
    for (int nt = 0; nt < 3; nt++) { s[nt][0] = s[nt][1] = 0.f; q[nt][0] = q[nt][1] = 0.f; }

#pragma unroll
    for (int mt = 0; mt < 2; mt++) {
        int r = row0 + mt * 16 + g;
#pragma unroll
        for (int nt = 0; nt < 3; nt++) {
            int n = nt * 8 + 2 * c;
            if (r < N_PTS) {
                float c0 = acc[mt][nt][0], c1 = acc[mt][nt][1];
                *(unsigned*)&g_yh[(size_t)r * C_OUT + n] = f2h2(c0, c1);
                s[nt][0] += c0; q[nt][0] += c0 * c0;
                s[nt][1] += c1; q[nt][1] += c1 * c1;
            }
            if (r + 8 < N_PTS) {
                float c2 = acc[mt][nt][2], c3 = acc[mt][nt][3];
                *(unsigned*)&g_yh[(size_t)(r + 8) * C_OUT + n] = f2h2(c2, c3);
                s[nt][0] += c2; q[nt][0] += c2 * c2;
                s[nt][1] += c3; q[nt][1] += c3 * c3;
            }
        }
    }
#pragma unroll
    for (int off = 16; off >= 4; off >>= 1) {
#pragma unroll
        for (int nt = 0; nt < 3; nt++) {
#pragma unroll
            for (int j = 0; j < 2; j++) {
                s[nt][j] += __shfl_down_sync(0xffffffffu, s[nt][j], off);
                q[nt][j] += __shfl_down_sync(0xffffffffu, q[nt][j], off);
            }
        }
    }
    if (g == 0) {
#pragma unroll
        for (int nt = 0; nt < 3; nt++) {
            int n = nt * 8 + 2 * c;
            atomicAdd(&ssum[n],     s[nt][0]);
            atomicAdd(&ssum[n + 1], s[nt][1]);
            atomicAdd(&ssq[n],      q[nt][0]);
            atomicAdd(&ssq[n + 1],  q[nt][1]);
        }
    }
    __syncthreads();
    if (tid < C_OUT) {
        atomicAdd(&g_s3[tid], ssum[tid]);
        atomicAdd(&g_q3[tid], ssq[tid]);
    }
    gdc_launch();
}

// ---- K7: out = bn3(y) + feats; y fp16 (uint2 = 4 halfs); block0 zeroes s1/q1 ----
__global__ void k7_out(const float* __restrict__ feats, float* __restrict__ out,
                       const float* __restrict__ g3, const float* __restrict__ b3) {
    __shared__ float ssc[C_OUT], ssh[C_OUT];
    int tid = threadIdx.x;
    gdc_wait();
    if (blockIdx.x == 0 && tid < C_HID) { g_s1[tid] = 0.f; g_q1[tid] = 0.f; }
    if (tid < C_OUT) {
        float m = g_s3[tid] * (1.0f / N_PTS);
        float v = g_q3[tid] * (1.0f / N_PTS) - m * m;
        float sc = g3[tid] * rsqrtf(v + EPS);
        ssc[tid] = sc;
        ssh[tid] = b3[tid] - m * sc;
    }
    __syncthreads();

    int i = blockIdx.x * blockDim.x + tid;   // 4-element group index
    if (i < N_PTS * C_OUT / 4) {
        int cb = (i % 6) * 4;
        uint2 yu = *(const uint2*)&g_yh[i * 4];
        float2 ylo = __half22float2(*(__half2*)&yu.x);
        float2 yhi = __half22float2(*(__half2*)&yu.y);
        float4 f  = *(const float4*)&feats[i * 4];
        float4 o;
        o.x = fmaf(ylo.x, ssc[cb + 0], ssh[cb + 0]) + f.x;
        o.y = fmaf(ylo.y, ssc[cb + 1], ssh[cb + 1]) + f.y;
        o.z = fmaf(yhi.x, ssc[cb + 2], ssh[cb + 2]) + f.z;
        o.w = fmaf(yhi.y, ssc[cb + 3], ssh[cb + 3]) + f.w;
        *(float4*)&out[i * 4] = o;
    }
}

// ---- PDL launch helper ----
template <typename... Args>
static void launch_pdl(void (*kern)(Args...), dim3 grid, dim3 block, Args... args) {
    cudaLaunchConfig_t cfg = {};
    cfg.gridDim = grid;
    cfg.blockDim = block;
    cfg.dynamicSmemBytes = 0;
    cfg.stream = 0;
    cudaLaunchAttribute attr[1];
    attr[0].id = cudaLaunchAttributeProgrammaticStreamSerialization;
    attr[0].val.programmaticStreamSerializationAllowed = 1;
    cfg.attrs = attr;
    cfg.numAttrs = 1;
    cudaLaunchKernelEx(&cfg, kern, args...);
}

extern "C" void kernel_launch(void* const* d_in, const int* in_sizes, int n_in,
                              void* d_out, int out_size) {
    const float* feats = (const float*)d_in[0];
    const float* w1    = (const float*)d_in[1];
    const float* g1    = (const float*)d_in[2];
    const float* b1    = (const float*)d_in[3];
    const float* w2    = (const float*)d_in[4];
    const float* g2    = (const float*)d_in[5];
    const float* b2    = (const float*)d_in[6];
    const float* w3    = (const float*)d_in[7];
    const float* g3    = (const float*)d_in[8];
    const float* b3    = (const float*)d_in[9];
    const int*   in_idx = (const int*)d_in[10];
    float* out = (float*)d_out;

    int nb1 = (N_PTS + R1 - 1) / R1;
    k1_gemm1<<<nb1, T1>>>(feats, w1);

    unsigned nba = (unsigned)(((size_t)N_PTS * C_HID / 8 + TA - 1) / TA);
    launch_pdl(k2_act, dim3(nba), dim3(TA), g1, b1);

    int nb3 = (N_PTS + R3 - 1) / R3;
    launch_pdl(k3_conv, dim3(nb3), dim3(T3), w2, in_idx);

    int nb5 = (N_PTS + R5T - 1) / R5T;
    launch_pdl(k5_tc, dim3(nb5), dim3(T5), w3, g2, b2);

    int total4 = N_PTS * C_OUT / 4;
    launch_pdl(k7_out, dim3((total4 + 255) / 256), dim3(256), feats, out, g3, b3);
}